// round 3
// baseline (speedup 1.0000x reference)
#include <cuda_runtime.h>
#include <math.h>

#define TT 256
#define BB 256
#define DD 512
#define LL 4
#define MLPD 2048
#define ROWS 512  // B * 2 tokens

// -------- device scratch (no allocations allowed) --------
__device__ float g_seq[ROWS * DD];       // (B*2, D): row = 2*b + tok (tok0=mem_tok, tok1=obs)
__device__ float g_qkv[ROWS * 3 * DD];   // q | k | v
__device__ float g_mlp[ROWS * MLPD];
__device__ unsigned g_count;             // monotonic grid-barrier counter
__device__ int g_done_bytes;             // 1 if dones stored as bytes, else int32

// Init node: reset barrier counter + detect dones dtype (deterministic).
__global__ void init_kernel(const unsigned char* __restrict__ p, int nbytes) {
    __shared__ int flag;
    if (threadIdx.x == 0) { flag = 0; g_count = 0u; }
    __syncthreads();
    int local = 0;
    for (int i = threadIdx.x; i < nbytes; i += blockDim.x)
        if ((i & 3) && p[i]) local = 1;
    if (local) atomicOr(&flag, 1);
    __syncthreads();
    if (threadIdx.x == 0) g_done_bytes = flag;
}

// Software grid barrier: monotonic counter, epoch-target passed by caller.
// __threadfence() is gpu-scope => CCTL.IVALL on sm_103a => L1D invalidated,
// so post-barrier global reads see other SMs' writes.
__device__ __forceinline__ void gsync(unsigned target) {
    __syncthreads();
    if (threadIdx.x == 0) {
        __threadfence();
        atomicAdd(&g_count, 1u);
        while (*((volatile unsigned*)&g_count) < target) __nanosleep(64);
        __threadfence();
    }
    __syncthreads();
}

struct Smem {
    float As[16][68];   // 68 stride: conflict-free + 16B-aligned rows (272B = 17*16)
    float Bs[16][64];
    float mu[64], rs[64];
    float p0[64][8], p1[64][8];
    float gate[64];
};

// MODE 0: gated mem @ mem_kernel -> g_seq even rows, plus obs copy -> odd rows
// MODE 1: LN1(seq) @ W(+bias) -> g_qkv          (W,bias pre-offset to tile col)
// MODE 2: attn(2-tok) A @ wo + bo + residual -> g_seq
// MODE 3: LN2(seq) @ w1 + b1, gelu(tanh) -> g_mlp
// MODE 4: g_mlp @ w2 + b2 + residual -> g_seq (+ out[t] odd rows if out_t)
template<int MODE>
__device__ __forceinline__ void do_tile(
    Smem& sm, int r0, int j0,
    const float* __restrict__ A0,       // mode0: prev memory (B x D)
    const float* __restrict__ obs_t,    // mode0
    const void*  __restrict__ dones, int done_off,
    const float* __restrict__ W,        // pre-offset to tile's first column
    const float* __restrict__ bias,     // pre-offset to tile's first column
    const float* __restrict__ lns, const float* __restrict__ lnb, // abs (per-layer)
    float* __restrict__ out_t)
{
    constexpr int KDIM = (MODE == 4) ? MLPD : DD;
    constexpr int LDB  = (MODE == 3) ? MLPD : DD;
    const int tid = threadIdx.x;

    // ---- prologues ----
    if (MODE == 0) {
        if (tid < 64) {
            int b = r0 + tid;
            bool done = g_done_bytes
                ? (((const unsigned char*)dones)[done_off + b] != 0)
                : (((const int*)dones)[done_off + b] != 0);
            sm.gate[tid] = done ? 0.f : 1.f;
        }
        #pragma unroll 4
        for (int i = tid; i < 64 * 64; i += 256) {
            int r = i >> 6, j = i & 63;
            int b = r0 + r;
            g_seq[(size_t)(2 * b + 1) * DD + j0 + j] = obs_t[(size_t)b * DD + j0 + j];
        }
        __syncthreads();
    }
    if (MODE == 1 || MODE == 3) {
        int r = tid >> 2, seg = tid & 3;
        const float4* p = (const float4*)(g_seq + (size_t)(r0 + r) * DD + seg * 128);
        float s = 0.f, q = 0.f;
        #pragma unroll
        for (int i = 0; i < 32; i++) {
            float4 v = p[i];
            s += v.x + v.y + v.z + v.w;
            q += v.x * v.x + v.y * v.y + v.z * v.z + v.w * v.w;
        }
        s += __shfl_xor_sync(0xffffffffu, s, 1);
        s += __shfl_xor_sync(0xffffffffu, s, 2);
        q += __shfl_xor_sync(0xffffffffu, q, 1);
        q += __shfl_xor_sync(0xffffffffu, q, 2);
        if (seg == 0) {
            float mu  = s * (1.f / 512.f);
            float var = q * (1.f / 512.f) - mu * mu;
            sm.mu[r] = mu;
            sm.rs[r] = rsqrtf(var + 1e-6f);
        }
        __syncthreads();
    }
    if (MODE == 2) {
        for (int pair = tid; pair < 512; pair += 256) {
            int r = pair >> 3, h = pair & 7;
            int R = r0 + r, b = R >> 1;
            const float4* qp  = (const float4*)(g_qkv + (size_t)R * 1536 + h * 64);
            const float4* kp0 = (const float4*)(g_qkv + (size_t)(2 * b) * 1536 + 512 + h * 64);
            const float4* kp1 = (const float4*)(g_qkv + (size_t)(2 * b + 1) * 1536 + 512 + h * 64);
            float s0 = 0.f, s1 = 0.f;
            #pragma unroll
            for (int i = 0; i < 16; i++) {
                float4 qv = qp[i], a = kp0[i], c = kp1[i];
                s0 += qv.x * a.x + qv.y * a.y + qv.z * a.z + qv.w * a.w;
                s1 += qv.x * c.x + qv.y * c.y + qv.z * c.z + qv.w * c.w;
            }
            s0 *= 0.125f; s1 *= 0.125f;   // 1/sqrt(64)
            float m  = fmaxf(s0, s1);
            float e0 = expf(s0 - m), e1 = expf(s1 - m);
            float inv = 1.f / (e0 + e1);
            sm.p0[r][h] = e0 * inv;
            sm.p1[r][h] = e1 * inv;
        }
        __syncthreads();
    }

    // ---- main GEMM: 64x64 tile, 16x16 threads, 4x4 microtile ----
    float acc[4][4];
    #pragma unroll
    for (int i = 0; i < 4; i++)
        #pragma unroll
        for (int j = 0; j < 4; j++) acc[i][j] = 0.f;

    const int ty4 = (tid >> 4) * 4;
    const int tx4 = (tid & 15) * 4;

    for (int k0 = 0; k0 < KDIM; k0 += 16) {
        #pragma unroll 4
        for (int i = tid; i < 1024; i += 256) {         // B tile (coalesced over j)
            int kk = i >> 6, j = i & 63;
            sm.Bs[kk][j] = W[(size_t)(k0 + kk) * LDB + j];
        }
        #pragma unroll 4
        for (int i = tid; i < 1024; i += 256) {         // A tile + transform
            int r = i >> 4, kk = i & 15;
            int R = r0 + r, kg = k0 + kk;
            float a;
            if (MODE == 0) {
                a = A0[(size_t)R * DD + kg] * sm.gate[r];
            } else if (MODE == 1 || MODE == 3) {
                float x = g_seq[(size_t)R * DD + kg];
                a = (x - sm.mu[r]) * sm.rs[r] * lns[kg] + lnb[kg];
            } else if (MODE == 2) {
                int b = R >> 1, h = kg >> 6;
                float v0 = g_qkv[(size_t)(2 * b) * 1536 + 1024 + kg];
                float v1 = g_qkv[(size_t)(2 * b + 1) * 1536 + 1024 + kg];
                a = sm.p0[r][h] * v0 + sm.p1[r][h] * v1;
            } else {
                a = g_mlp[(size_t)R * MLPD + kg];
            }
            sm.As[kk][r] = a;
        }
        __syncthreads();
        #pragma unroll
        for (int kk = 0; kk < 16; kk++) {
            float av[4], bv[4];
            #pragma unroll
            for (int i = 0; i < 4; i++) av[i] = sm.As[kk][ty4 + i];
            #pragma unroll
            for (int j = 0; j < 4; j++) bv[j] = sm.Bs[kk][tx4 + j];
            #pragma unroll
            for (int i = 0; i < 4; i++)
                #pragma unroll
                for (int j = 0; j < 4; j++)
                    acc[i][j] = fmaf(av[i], bv[j], acc[i][j]);
        }
        __syncthreads();
    }

    // ---- epilogue ----
    #pragma unroll
    for (int i = 0; i < 4; i++) {
        int R = r0 + ty4 + i;
        #pragma unroll
        for (int j = 0; j < 4; j++) {
            int jg = j0 + tx4 + j;
            float v = acc[i][j];
            if (MODE == 0) {
                g_seq[(size_t)(2 * R) * DD + jg] = v;
            } else if (MODE == 1) {
                g_qkv[(size_t)R * 1536 + jg] = v + bias[tx4 + j];
            } else if (MODE == 2) {
                size_t idx = (size_t)R * DD + jg;
                v += bias[tx4 + j] + g_seq[idx];
                g_seq[idx] = v;
            } else if (MODE == 3) {
                v += bias[tx4 + j];
                float x3 = v * v * v;   // jax.nn.gelu default = tanh approx
                v = 0.5f * v * (1.f + tanhf(0.7978845608028654f * (v + 0.044715f * x3)));
                g_mlp[(size_t)R * MLPD + jg] = v;
            } else {
                size_t idx = (size_t)R * DD + jg;
                v += bias[tx4 + j] + g_seq[idx];
                g_seq[idx] = v;
                if (out_t != nullptr && (R & 1))
                    out_t[(size_t)(R >> 1) * DD + jg] = v;  // new_mem = seq[:,1,:]
            }
        }
    }
}

__global__ __launch_bounds__(256)
void rmt_persistent(int G,
                    const float* __restrict__ obs, const void* __restrict__ dones,
                    const float* __restrict__ memory, const float* __restrict__ mem_kernel,
                    const float* __restrict__ ln1_s, const float* __restrict__ ln1_b,
                    const float* __restrict__ wq, const float* __restrict__ bq,
                    const float* __restrict__ wk, const float* __restrict__ bk,
                    const float* __restrict__ wv, const float* __restrict__ bv,
                    const float* __restrict__ wo, const float* __restrict__ bo,
                    const float* __restrict__ ln2_s, const float* __restrict__ ln2_b,
                    const float* __restrict__ w1, const float* __restrict__ b1,
                    const float* __restrict__ w2, const float* __restrict__ b2,
                    float* __restrict__ out)
{
    __shared__ Smem sm;
    const int bid = blockIdx.x;
    unsigned ep = 0;

    for (int t = 0; t < TT; t++) {
        const float* memprev = (t == 0) ? memory : (out + (size_t)(t - 1) * BB * DD);
        const float* obs_t = obs + (size_t)t * BB * DD;

        // P0: 32 tiles (256 mem rows x 512 cols)
        for (int tile = bid; tile < 32; tile += G) {
            do_tile<0>(sm, (tile >> 3) * 64, (tile & 7) * 64,
                       memprev, obs_t, dones, t * BB,
                       mem_kernel + (tile & 7) * 64, nullptr, nullptr, nullptr, nullptr);
        }
        ep++; gsync(ep * (unsigned)G);

        for (int l = 0; l < LL; l++) {
            size_t dd = (size_t)l * DD * DD;
            const float* l1s = ln1_s + (size_t)l * DD;
            const float* l1b = ln1_b + (size_t)l * DD;
            const float* l2s = ln2_s + (size_t)l * DD;
            const float* l2b = ln2_b + (size_t)l * DD;

            // P1: QKV, 192 tiles (512 x 1536)
            for (int tile = bid; tile < 192; tile += G) {
                int tr = tile / 24, tc = tile % 24;
                int j0 = tc * 64;
                int m = j0 >> 9, jj0 = j0 & 511;
                const float* W = ((m == 0) ? wq : (m == 1) ? wk : wv) + dd + jj0;
                const float* B = ((m == 0) ? bq : (m == 1) ? bk : bv) + (size_t)l * DD + jj0;
                do_tile<1>(sm, tr * 64, j0, nullptr, nullptr, nullptr, 0,
                           W, B, l1s, l1b, nullptr);
            }
            ep++; gsync(ep * (unsigned)G);

            // P2: attn + O-proj + residual, 64 tiles (512 x 512)
            for (int tile = bid; tile < 64; tile += G) {
                int j0 = (tile & 7) * 64;
                do_tile<2>(sm, (tile >> 3) * 64, j0, nullptr, nullptr, nullptr, 0,
                           wo + dd + j0, bo + (size_t)l * DD + j0, nullptr, nullptr, nullptr);
            }
            ep++; gsync(ep * (unsigned)G);

            // P3: MLP1 + gelu, 256 tiles (512 x 2048)
            for (int tile = bid; tile < 256; tile += G) {
                int j0 = (tile & 31) * 64;
                do_tile<3>(sm, (tile >> 5) * 64, j0, nullptr, nullptr, nullptr, 0,
                           w1 + (size_t)l * DD * MLPD + j0, b1 + (size_t)l * MLPD + j0,
                           l2s, l2b, nullptr);
            }
            ep++; gsync(ep * (unsigned)G);

            // P4: MLP2 + residual (+ out write on last layer), 64 tiles (512 x 512, K=2048)
            float* outp = (l == LL - 1) ? (out + (size_t)t * BB * DD) : nullptr;
            for (int tile = bid; tile < 64; tile += G) {
                int j0 = (tile & 7) * 64;
                do_tile<4>(sm, (tile >> 3) * 64, j0, nullptr, nullptr, nullptr, 0,
                           w2 + (size_t)l * MLPD * DD + j0, b2 + (size_t)l * DD + j0,
                           nullptr, nullptr, outp);
            }
            ep++; gsync(ep * (unsigned)G);
        }
    }
}

extern "C" void kernel_launch(void* const* d_in, const int* in_sizes, int n_in,
                              void* d_out, int out_size) {
    const float* obs        = (const float*)d_in[0];
    const void*  dones      = d_in[1];
    const float* memory     = (const float*)d_in[2];
    const float* mem_kernel = (const float*)d_in[3];
    const float* ln1_s = (const float*)d_in[4];
    const float* ln1_b = (const float*)d_in[5];
    const float* wq = (const float*)d_in[6];
    const float* bq = (const float*)d_in[7];
    const float* wk = (const float*)d_in[8];
    const float* bk = (const float*)d_in[9];
    const float* wv = (const float*)d_in[10];
    const float* bv = (const float*)d_in[11];
    const float* wo = (const float*)d_in[12];
    const float* bo = (const float*)d_in[13];
    const float* ln2_s = (const float*)d_in[14];
    const float* ln2_b = (const float*)d_in[15];
    const float* w1 = (const float*)d_in[16];
    const float* b1 = (const float*)d_in[17];
    const float* w2 = (const float*)d_in[18];
    const float* b2 = (const float*)d_in[19];
    float* out = (float*)d_out;

    // Co-resident grid sizing (host-side, not captured as work).
    int dev = 0;
    cudaGetDevice(&dev);
    int sms = 148;
    cudaDeviceGetAttribute(&sms, cudaDevAttrMultiProcessorCount, dev);
    int nb = 1;
    cudaOccupancyMaxActiveBlocksPerMultiprocessor(&nb, rmt_persistent, 256, 0);
    if (nb < 1) nb = 1;
    int G = sms * nb;
    if (G > 256) G = 256;   // max tiles in any phase

    init_kernel<<<1, 256>>>((const unsigned char*)dones, TT * BB);
    rmt_persistent<<<G, 256>>>(G, obs, dones, memory, mem_kernel,
                               ln1_s, ln1_b, wq, bq, wk, bk, wv, bv, wo, bo,
                               ln2_s, ln2_b, w1, b1, w2, b2, out);
}

// round 4
// speedup vs baseline: 1.0019x; 1.0019x over previous
#include <cuda_runtime.h>
#include <math.h>

#define TT 256
#define BB 256
#define DD 512
#define LL 4
#define MLPD 2048
#define ROWS 512  // B * 2 tokens

// -------- device scratch (no allocations allowed) --------
__device__ float g_seq[ROWS * DD];       // (B*2, D): row = 2*b + tok (tok0=mem_tok, tok1=obs)
__device__ float g_qkv[ROWS * 3 * DD];   // q | k | v
__device__ float g_mlp[ROWS * MLPD];
__device__ unsigned g_count;             // monotonic grid-barrier counter
__device__ int g_done_bytes;             // 1 if dones stored as bytes, else int32

// Init node: reset barrier counter + detect dones dtype (deterministic).
__global__ void init_kernel(const unsigned char* __restrict__ p, int nbytes) {
    __shared__ int flag;
    if (threadIdx.x == 0) { flag = 0; g_count = 0u; }
    __syncthreads();
    int local = 0;
    for (int i = threadIdx.x; i < nbytes; i += blockDim.x)
        if ((i & 3) && p[i]) local = 1;
    if (local) atomicOr(&flag, 1);
    __syncthreads();
    if (threadIdx.x == 0) g_done_bytes = flag;
}

// Software grid barrier: monotonic counter, epoch-target passed by caller.
// __threadfence() is gpu-scope => CCTL.IVALL on sm_103a => L1D invalidated,
// so post-barrier global reads see other SMs' writes.
__device__ __forceinline__ void gsync(unsigned target) {
    __syncthreads();
    if (threadIdx.x == 0) {
        __threadfence();
        atomicAdd(&g_count, 1u);
        while (*((volatile unsigned*)&g_count) < target) __nanosleep(64);
        __threadfence();
    }
    __syncthreads();
}

struct Smem {
    float As[16][68];   // 68 stride: conflict-free + 16B-aligned rows (272B = 17*16)
    float Bs[16][64];
    float mu[64], rs[64];
    float p0[64][8], p1[64][8];
    float gate[64];
};

// MODE 0: gated mem @ mem_kernel -> g_seq even rows, plus obs copy -> odd rows
// MODE 1: LN1(seq) @ W(+bias) -> g_qkv          (W,bias pre-offset to tile col)
// MODE 2: attn(2-tok) A @ wo + bo + residual -> g_seq
// MODE 3: LN2(seq) @ w1 + b1, gelu(tanh) -> g_mlp
// MODE 4: g_mlp @ w2 + b2 + residual -> g_seq (+ out[t] odd rows if out_t)
template<int MODE>
__device__ __forceinline__ void do_tile(
    Smem& sm, int r0, int j0,
    const float* __restrict__ A0,       // mode0: prev memory (B x D)
    const float* __restrict__ obs_t,    // mode0
    const void*  __restrict__ dones, int done_off,
    const float* __restrict__ W,        // pre-offset to tile's first column
    const float* __restrict__ bias,     // pre-offset to tile's first column
    const float* __restrict__ lns, const float* __restrict__ lnb, // abs (per-layer)
    float* __restrict__ out_t)
{
    constexpr int KDIM = (MODE == 4) ? MLPD : DD;
    constexpr int LDB  = (MODE == 3) ? MLPD : DD;
    const int tid = threadIdx.x;

    // ---- prologues ----
    if (MODE == 0) {
        if (tid < 64) {
            int b = r0 + tid;
            bool done = g_done_bytes
                ? (((const unsigned char*)dones)[done_off + b] != 0)
                : (((const int*)dones)[done_off + b] != 0);
            sm.gate[tid] = done ? 0.f : 1.f;
        }
        #pragma unroll 4
        for (int i = tid; i < 64 * 64; i += 256) {
            int r = i >> 6, j = i & 63;
            int b = r0 + r;
            g_seq[(size_t)(2 * b + 1) * DD + j0 + j] = obs_t[(size_t)b * DD + j0 + j];
        }
        __syncthreads();
    }
    if (MODE == 1 || MODE == 3) {
        int r = tid >> 2, seg = tid & 3;
        const float4* p = (const float4*)(g_seq + (size_t)(r0 + r) * DD + seg * 128);
        float s = 0.f, q = 0.f;
        #pragma unroll
        for (int i = 0; i < 32; i++) {
            float4 v = p[i];
            s += v.x + v.y + v.z + v.w;
            q += v.x * v.x + v.y * v.y + v.z * v.z + v.w * v.w;
        }
        s += __shfl_xor_sync(0xffffffffu, s, 1);
        s += __shfl_xor_sync(0xffffffffu, s, 2);
        q += __shfl_xor_sync(0xffffffffu, q, 1);
        q += __shfl_xor_sync(0xffffffffu, q, 2);
        if (seg == 0) {
            float mu  = s * (1.f / 512.f);
            float var = q * (1.f / 512.f) - mu * mu;
            sm.mu[r] = mu;
            sm.rs[r] = rsqrtf(var + 1e-6f);
        }
        __syncthreads();
    }
    if (MODE == 2) {
        for (int pair = tid; pair < 512; pair += 256) {
            int r = pair >> 3, h = pair & 7;
            int R = r0 + r, b = R >> 1;
            const float4* qp  = (const float4*)(g_qkv + (size_t)R * 1536 + h * 64);
            const float4* kp0 = (const float4*)(g_qkv + (size_t)(2 * b) * 1536 + 512 + h * 64);
            const float4* kp1 = (const float4*)(g_qkv + (size_t)(2 * b + 1) * 1536 + 512 + h * 64);
            float s0 = 0.f, s1 = 0.f;
            #pragma unroll
            for (int i = 0; i < 16; i++) {
                float4 qv = qp[i], a = kp0[i], c = kp1[i];
                s0 += qv.x * a.x + qv.y * a.y + qv.z * a.z + qv.w * a.w;
                s1 += qv.x * c.x + qv.y * c.y + qv.z * c.z + qv.w * c.w;
            }
            s0 *= 0.125f; s1 *= 0.125f;   // 1/sqrt(64)
            float m  = fmaxf(s0, s1);
            float e0 = expf(s0 - m), e1 = expf(s1 - m);
            float inv = 1.f / (e0 + e1);
            sm.p0[r][h] = e0 * inv;
            sm.p1[r][h] = e1 * inv;
        }
        __syncthreads();
    }

    // ---- main GEMM: 64x64 tile, 16x16 threads, 4x4 microtile ----
    float acc[4][4];
    #pragma unroll
    for (int i = 0; i < 4; i++)
        #pragma unroll
        for (int j = 0; j < 4; j++) acc[i][j] = 0.f;

    const int ty4 = (tid >> 4) * 4;
    const int tx4 = (tid & 15) * 4;

    for (int k0 = 0; k0 < KDIM; k0 += 16) {
        #pragma unroll 4
        for (int i = tid; i < 1024; i += 256) {         // B tile (coalesced over j)
            int kk = i >> 6, j = i & 63;
            sm.Bs[kk][j] = W[(size_t)(k0 + kk) * LDB + j];
        }
        #pragma unroll 4
        for (int i = tid; i < 1024; i += 256) {         // A tile + transform
            int r = i >> 4, kk = i & 15;
            int R = r0 + r, kg = k0 + kk;
            float a;
            if (MODE == 0) {
                a = A0[(size_t)R * DD + kg] * sm.gate[r];
            } else if (MODE == 1 || MODE == 3) {
                float x = g_seq[(size_t)R * DD + kg];
                a = (x - sm.mu[r]) * sm.rs[r] * lns[kg] + lnb[kg];
            } else if (MODE == 2) {
                int b = R >> 1, h = kg >> 6;
                float v0 = g_qkv[(size_t)(2 * b) * 1536 + 1024 + kg];
                float v1 = g_qkv[(size_t)(2 * b + 1) * 1536 + 1024 + kg];
                a = sm.p0[r][h] * v0 + sm.p1[r][h] * v1;
            } else {
                a = g_mlp[(size_t)R * MLPD + kg];
            }
            sm.As[kk][r] = a;
        }
        __syncthreads();
        #pragma unroll
        for (int kk = 0; kk < 16; kk++) {
            float av[4], bv[4];
            #pragma unroll
            for (int i = 0; i < 4; i++) av[i] = sm.As[kk][ty4 + i];
            #pragma unroll
            for (int j = 0; j < 4; j++) bv[j] = sm.Bs[kk][tx4 + j];
            #pragma unroll
            for (int i = 0; i < 4; i++)
                #pragma unroll
                for (int j = 0; j < 4; j++)
                    acc[i][j] = fmaf(av[i], bv[j], acc[i][j]);
        }
        __syncthreads();
    }

    // ---- epilogue ----
    #pragma unroll
    for (int i = 0; i < 4; i++) {
        int R = r0 + ty4 + i;
        #pragma unroll
        for (int j = 0; j < 4; j++) {
            int jg = j0 + tx4 + j;
            float v = acc[i][j];
            if (MODE == 0) {
                g_seq[(size_t)(2 * R) * DD + jg] = v;
            } else if (MODE == 1) {
                g_qkv[(size_t)R * 1536 + jg] = v + bias[tx4 + j];
            } else if (MODE == 2) {
                size_t idx = (size_t)R * DD + jg;
                v += bias[tx4 + j] + g_seq[idx];
                g_seq[idx] = v;
            } else if (MODE == 3) {
                v += bias[tx4 + j];
                float x3 = v * v * v;   // jax.nn.gelu default = tanh approx
                v = 0.5f * v * (1.f + tanhf(0.7978845608028654f * (v + 0.044715f * x3)));
                g_mlp[(size_t)R * MLPD + jg] = v;
            } else {
                size_t idx = (size_t)R * DD + jg;
                v += bias[tx4 + j] + g_seq[idx];
                g_seq[idx] = v;
                if (out_t != nullptr && (R & 1))
                    out_t[(size_t)(R >> 1) * DD + jg] = v;  // new_mem = seq[:,1,:]
            }
        }
    }
}

__global__ __launch_bounds__(256)
void rmt_persistent(int G,
                    const float* __restrict__ obs, const void* __restrict__ dones,
                    const float* __restrict__ memory, const float* __restrict__ mem_kernel,
                    const float* __restrict__ ln1_s, const float* __restrict__ ln1_b,
                    const float* __restrict__ wq, const float* __restrict__ bq,
                    const float* __restrict__ wk, const float* __restrict__ bk,
                    const float* __restrict__ wv, const float* __restrict__ bv,
                    const float* __restrict__ wo, const float* __restrict__ bo,
                    const float* __restrict__ ln2_s, const float* __restrict__ ln2_b,
                    const float* __restrict__ w1, const float* __restrict__ b1,
                    const float* __restrict__ w2, const float* __restrict__ b2,
                    float* __restrict__ out)
{
    __shared__ Smem sm;
    const int bid = blockIdx.x;
    unsigned ep = 0;

    for (int t = 0; t < TT; t++) {
        const float* memprev = (t == 0) ? memory : (out + (size_t)(t - 1) * BB * DD);
        const float* obs_t = obs + (size_t)t * BB * DD;

        // P0: 32 tiles (256 mem rows x 512 cols)
        for (int tile = bid; tile < 32; tile += G) {
            do_tile<0>(sm, (tile >> 3) * 64, (tile & 7) * 64,
                       memprev, obs_t, dones, t * BB,
                       mem_kernel + (tile & 7) * 64, nullptr, nullptr, nullptr, nullptr);
        }
        ep++; gsync(ep * (unsigned)G);

        for (int l = 0; l < LL; l++) {
            size_t dd = (size_t)l * DD * DD;
            const float* l1s = ln1_s + (size_t)l * DD;
            const float* l1b = ln1_b + (size_t)l * DD;
            const float* l2s = ln2_s + (size_t)l * DD;
            const float* l2b = ln2_b + (size_t)l * DD;

            // P1: QKV, 192 tiles (512 x 1536)
            for (int tile = bid; tile < 192; tile += G) {
                int tr = tile / 24, tc = tile % 24;
                int j0 = tc * 64;
                int m = j0 >> 9, jj0 = j0 & 511;
                const float* W = ((m == 0) ? wq : (m == 1) ? wk : wv) + dd + jj0;
                const float* B = ((m == 0) ? bq : (m == 1) ? bk : bv) + (size_t)l * DD + jj0;
                do_tile<1>(sm, tr * 64, j0, nullptr, nullptr, nullptr, 0,
                           W, B, l1s, l1b, nullptr);
            }
            ep++; gsync(ep * (unsigned)G);

            // P2: attn + O-proj + residual, 64 tiles (512 x 512)
            for (int tile = bid; tile < 64; tile += G) {
                int j0 = (tile & 7) * 64;
                do_tile<2>(sm, (tile >> 3) * 64, j0, nullptr, nullptr, nullptr, 0,
                           wo + dd + j0, bo + (size_t)l * DD + j0, nullptr, nullptr, nullptr);
            }
            ep++; gsync(ep * (unsigned)G);

            // P3: MLP1 + gelu, 256 tiles (512 x 2048)
            for (int tile = bid; tile < 256; tile += G) {
                int j0 = (tile & 31) * 64;
                do_tile<3>(sm, (tile >> 5) * 64, j0, nullptr, nullptr, nullptr, 0,
                           w1 + (size_t)l * DD * MLPD + j0, b1 + (size_t)l * MLPD + j0,
                           l2s, l2b, nullptr);
            }
            ep++; gsync(ep * (unsigned)G);

            // P4: MLP2 + residual (+ out write on last layer), 64 tiles (512 x 512, K=2048)
            float* outp = (l == LL - 1) ? (out + (size_t)t * BB * DD) : nullptr;
            for (int tile = bid; tile < 64; tile += G) {
                int j0 = (tile & 7) * 64;
                do_tile<4>(sm, (tile >> 3) * 64, j0, nullptr, nullptr, nullptr, 0,
                           w2 + (size_t)l * MLPD * DD + j0, b2 + (size_t)l * DD + j0,
                           nullptr, nullptr, outp);
            }
            ep++; gsync(ep * (unsigned)G);
        }
    }
}

extern "C" void kernel_launch(void* const* d_in, const int* in_sizes, int n_in,
                              void* d_out, int out_size) {
    const float* obs        = (const float*)d_in[0];
    const void*  dones      = d_in[1];
    const float* memory     = (const float*)d_in[2];
    const float* mem_kernel = (const float*)d_in[3];
    const float* ln1_s = (const float*)d_in[4];
    const float* ln1_b = (const float*)d_in[5];
    const float* wq = (const float*)d_in[6];
    const float* bq = (const float*)d_in[7];
    const float* wk = (const float*)d_in[8];
    const float* bk = (const float*)d_in[9];
    const float* wv = (const float*)d_in[10];
    const float* bv = (const float*)d_in[11];
    const float* wo = (const float*)d_in[12];
    const float* bo = (const float*)d_in[13];
    const float* ln2_s = (const float*)d_in[14];
    const float* ln2_b = (const float*)d_in[15];
    const float* w1 = (const float*)d_in[16];
    const float* b1 = (const float*)d_in[17];
    const float* w2 = (const float*)d_in[18];
    const float* b2 = (const float*)d_in[19];
    float* out = (float*)d_out;

    // Co-resident grid sizing (host-side, not captured as work).
    int dev = 0;
    cudaGetDevice(&dev);
    int sms = 148;
    cudaDeviceGetAttribute(&sms, cudaDevAttrMultiProcessorCount, dev);
    int nb = 1;
    cudaOccupancyMaxActiveBlocksPerMultiprocessor(&nb, rmt_persistent, 256, 0);
    if (nb < 1) nb = 1;
    int G = sms * nb;
    if (G > 256) G = 256;   // max tiles in any phase

    init_kernel<<<1, 256>>>((const unsigned char*)dones, TT * BB);
    rmt_persistent<<<G, 256>>>(G, obs, dones, memory, mem_kernel,
                               ln1_s, ln1_b, wq, bq, wk, bk, wv, bv, wo, bo,
                               ln2_s, ln2_b, w1, b1, w2, b2, out);
}